// round 1
// baseline (speedup 1.0000x reference)
#include <cuda_runtime.h>
#include <math.h>

#define T_ 2000
#define B_ 64
#define D_ 512
#define H_ 512
#define TB_ (T_*B_)

// ---- scratch (static device allocations; no cudaMalloc allowed) ----
__device__ float g_wh[TB_*H_];     // 262 MB
__device__ float g_wz[TB_*H_];     // 262 MB
__device__ float g_h1[TB_*H_];     // 262 MB (layer-1 output)
__device__ float g_hbuf[B_*H_];    // current hidden state
__device__ float g_zhbuf[B_*H_];   // z * h staging
__device__ unsigned int g_bar[8];  // one barrier counter per batch-group

// =====================================================================
// Stage A: fused dual projection  owh = X@Wh^T + bh, owz = X@Wz^T + bz
// X: [M,512] row-major, Wh/Wz: [512,512] row-major (row = out neuron)
// Tile: 64(M) x 64(N) x 32(K). 256 threads, 4x4 register tile per matrix.
// =====================================================================
__global__ void __launch_bounds__(256) proj_kernel(
    const float* __restrict__ X,
    const float* __restrict__ Wh, const float* __restrict__ Wz,
    const float* __restrict__ bh, const float* __restrict__ bz,
    float* __restrict__ owh, float* __restrict__ owz)
{
    __shared__ float As[32*64];
    __shared__ float Bhs[32*64];
    __shared__ float Bzs[32*64];

    const int tid = threadIdx.x;
    const int n0 = blockIdx.x * 64;
    const long m0 = (long)blockIdx.y * 64;
    const int pm = tid & 15;      // 16 positions along M
    const int pn = tid >> 4;      // 16 positions along N

    float ah[4][4], az[4][4];
#pragma unroll
    for (int i = 0; i < 4; i++)
#pragma unroll
        for (int j = 0; j < 4; j++) { ah[i][j] = 0.f; az[i][j] = 0.f; }

    for (int k0 = 0; k0 < 512; k0 += 32) {
        __syncthreads();
#pragma unroll
        for (int q = 0; q < 2; q++) {
            int c = tid + 256*q;            // 0..511
            int row = c >> 3;               // 0..63
            int col4 = (c & 7) * 4;         // 0..28
            float4 xa = *(const float4*)&X[(m0 + row)*512 + k0 + col4];
            As[(col4+0)*64+row] = xa.x; As[(col4+1)*64+row] = xa.y;
            As[(col4+2)*64+row] = xa.z; As[(col4+3)*64+row] = xa.w;
            float4 wa = *(const float4*)&Wh[(long)(n0 + row)*512 + k0 + col4];
            Bhs[(col4+0)*64+row] = wa.x; Bhs[(col4+1)*64+row] = wa.y;
            Bhs[(col4+2)*64+row] = wa.z; Bhs[(col4+3)*64+row] = wa.w;
            float4 za = *(const float4*)&Wz[(long)(n0 + row)*512 + k0 + col4];
            Bzs[(col4+0)*64+row] = za.x; Bzs[(col4+1)*64+row] = za.y;
            Bzs[(col4+2)*64+row] = za.z; Bzs[(col4+3)*64+row] = za.w;
        }
        __syncthreads();
#pragma unroll
        for (int kk = 0; kk < 32; kk++) {
            float4 a  = *(float4*)&As [kk*64 + pm*4];
            float4 bh4 = *(float4*)&Bhs[kk*64 + pn*4];
            float4 bz4 = *(float4*)&Bzs[kk*64 + pn*4];
            float av[4] = {a.x, a.y, a.z, a.w};
            float hv[4] = {bh4.x, bh4.y, bh4.z, bh4.w};
            float zv[4] = {bz4.x, bz4.y, bz4.z, bz4.w};
#pragma unroll
            for (int i = 0; i < 4; i++)
#pragma unroll
                for (int j = 0; j < 4; j++) {
                    ah[i][j] += av[i]*hv[j];
                    az[i][j] += av[i]*zv[j];
                }
        }
    }

    float bb_h[4], bb_z[4];
#pragma unroll
    for (int j = 0; j < 4; j++) { bb_h[j] = bh[n0 + pn*4 + j]; bb_z[j] = bz[n0 + pn*4 + j]; }
#pragma unroll
    for (int i = 0; i < 4; i++) {
        long r = (m0 + pm*4 + i)*512 + n0 + pn*4;
        float4 oh, oz;
        oh.x = ah[i][0]+bb_h[0]; oh.y = ah[i][1]+bb_h[1];
        oh.z = ah[i][2]+bb_h[2]; oh.w = ah[i][3]+bb_h[3];
        oz.x = az[i][0]+bb_z[0]; oz.y = az[i][1]+bb_z[1];
        oz.z = az[i][2]+bb_z[2]; oz.w = az[i][3]+bb_z[3];
        *(float4*)&owh[r] = oh;
        *(float4*)&owz[r] = oz;
    }
}

// =====================================================================
// Stage B: persistent GRU scan.
// Grid: 128 CTAs = 8 batch-groups (8 batches each) x 16 H-slices (32 each).
// Each CTA keeps Uz/Uh slices [512 x 32] in SMEM (j-major).
// Per step: GEMM-z -> sigmoid -> write z*h -> group barrier ->
//           GEMM-h -> tanh -> write h -> group barrier.
// =====================================================================
#define SCAN_SMEM_BYTES (40960*4)

__device__ __forceinline__ void group_barrier(unsigned int* bar, int gb, unsigned int target)
{
    __syncthreads();
    if (threadIdx.x == 0) {
        __threadfence();
        atomicAdd(&bar[gb], 1u);
        while (*((volatile unsigned int*)&bar[gb]) < target) { }
        __threadfence();
    }
    __syncthreads();
}

__device__ __forceinline__ void load_hx(float* __restrict__ hx,
                                        const float* __restrict__ src, int b0)
{
    const int tid = threadIdx.x;
#pragma unroll
    for (int q = 0; q < 4; q++) {
        int c = tid + 256*q;          // 0..1023
        int b = c >> 7;               // 0..7
        int jc = c & 127;             // 0..127
        float4 v = *(const float4*)&src[(b0 + b)*512 + jc*4];
        int jj = jc*4;
        float vv[4] = {v.x, v.y, v.z, v.w};
#pragma unroll
        for (int e = 0; e < 4; e++) {
            int j = jj + e;
            hx[j*8 + ((((b>>2) ^ (j&1)))<<2) + (b&3)] = vv[e];
        }
    }
}

__global__ void __launch_bounds__(256) scan_kernel(
    const float* __restrict__ wh, const float* __restrict__ wz,
    const float* __restrict__ Uh, const float* __restrict__ Uz,
    float* __restrict__ out,
    float* __restrict__ hbuf, float* __restrict__ zhbuf,
    unsigned int* __restrict__ bar)
{
    extern __shared__ float sm[];
    float* Uzs = sm;                 // 512*32
    float* Uhs = sm + 16384;         // 512*32
    float* hx  = sm + 32768;         // 512*8 (swizzled, transposed)
    float* red = sm + 36864;         // 16*256

    const int tid = threadIdx.x;
    const int gb = blockIdx.x >> 4;   // batch group 0..7
    const int gh = blockIdx.x & 15;   // h slice 0..15
    const int b0 = gb * 8;
    const int i0 = gh * 32;

    // Load U slices into SMEM (one-time)
    for (int idx = tid; idx < 32*512; idx += 256) {
        int i = idx >> 9;
        int j = idx & 511;
        Uzs[j*32 + i] = Uz[(i0 + i)*512 + j];
        Uhs[j*32 + i] = Uh[(i0 + i)*512 + j];
    }

    // GEMM thread layout: tid = ks*16 + pos ; warp = 2 ks x 16 pos
    const int ks = tid >> 4;          // K-split 0..15 (j in [ks*32, ks*32+32))
    const int pos = tid & 15;
    const int pb = pos >> 3;          // 0..1 (4 batches each)
    const int pi = pos & 7;           // 0..7 (4 outputs each)
    const int jbase = ks * 32;

    // Output mapping after reduction: thread tid owns (b_local, i_local)
    const int bl = tid >> 5;          // 0..7
    const int il = tid & 31;          // 0..31
    const int jg = i0 + il;           // global output index
    const int hprev_off = jg*8 + ((((bl>>2) ^ (jg&1)))<<2) + (bl&3);

    for (int t = 0; t < T_; t++) {
        // Prefetch this thread's wz/wh early (independent of h)
        long base = ((long)t*B_ + (b0 + bl))*(long)H_ + jg;
        float wzv = wz[base];
        float whv = wh[base];

        load_hx(hx, hbuf, b0);
        __syncthreads();

        // ---- GEMM z: pf[b][i] = sum_j h[b,j] * Uz[i,j] (partial over ks) ----
        float pf[4][4];
#pragma unroll
        for (int i = 0; i < 4; i++)
#pragma unroll
            for (int j = 0; j < 4; j++) pf[i][j] = 0.f;
#pragma unroll
        for (int kk = 0; kk < 32; kk++) {
            int j = jbase + kk;
            float4 hv = *(float4*)&hx[j*8 + ((pb ^ (j&1))<<2)];
            float4 uv = *(float4*)&Uzs[j*32 + pi*4];
            float hvv[4] = {hv.x, hv.y, hv.z, hv.w};
            float uvv[4] = {uv.x, uv.y, uv.z, uv.w};
#pragma unroll
            for (int b = 0; b < 4; b++)
#pragma unroll
                for (int i = 0; i < 4; i++) pf[b][i] += hvv[b]*uvv[i];
        }
#pragma unroll
        for (int b = 0; b < 4; b++)
#pragma unroll
            for (int i = 0; i < 4; i++)
                red[ks*256 + (pb*4 + b)*32 + pi*4 + i] = pf[b][i];
        __syncthreads();

        float s = 0.f;
#pragma unroll
        for (int k2 = 0; k2 < 16; k2++) s += red[k2*256 + tid];

        float z = 1.f / (1.f + expf(-(s + wzv)));
        float hp = hx[hprev_off];
        float zh = z * hp;
        zhbuf[(b0 + bl)*512 + jg] = zh;

        group_barrier(bar, gb, (unsigned)(2*t + 1) * 16u);

        load_hx(hx, zhbuf, b0);
        __syncthreads();

        // ---- GEMM h: sum_j (z*h)[b,j] * Uh[i,j] ----
#pragma unroll
        for (int i = 0; i < 4; i++)
#pragma unroll
            for (int j = 0; j < 4; j++) pf[i][j] = 0.f;
#pragma unroll
        for (int kk = 0; kk < 32; kk++) {
            int j = jbase + kk;
            float4 hv = *(float4*)&hx[j*8 + ((pb ^ (j&1))<<2)];
            float4 uv = *(float4*)&Uhs[j*32 + pi*4];
            float hvv[4] = {hv.x, hv.y, hv.z, hv.w};
            float uvv[4] = {uv.x, uv.y, uv.z, uv.w};
#pragma unroll
            for (int b = 0; b < 4; b++)
#pragma unroll
                for (int i = 0; i < 4; i++) pf[b][i] += hvv[b]*uvv[i];
        }
#pragma unroll
        for (int b = 0; b < 4; b++)
#pragma unroll
            for (int i = 0; i < 4; i++)
                red[ks*256 + (pb*4 + b)*32 + pi*4 + i] = pf[b][i];
        __syncthreads();

        float s2 = 0.f;
#pragma unroll
        for (int k2 = 0; k2 < 16; k2++) s2 += red[k2*256 + tid];

        float hc = tanhf(s2 + whv);
        float hn = zh + (1.f - z)*hc;
        hbuf[(b0 + bl)*512 + jg] = hn;
        out[base] = hn;

        group_barrier(bar, gb, (unsigned)(2*t + 2) * 16u);
    }
}

// =====================================================================
extern "C" void kernel_launch(void* const* d_in, const int* in_sizes, int n_in,
                              void* d_out, int out_size)
{
    const float* x   = (const float*)d_in[0];
    const float* Wh0 = (const float*)d_in[1];
    const float* bh0 = (const float*)d_in[2];
    const float* Wz0 = (const float*)d_in[3];
    const float* bz0 = (const float*)d_in[4];
    const float* Uh0 = (const float*)d_in[5];
    const float* Uz0 = (const float*)d_in[6];
    const float* Wh1 = (const float*)d_in[7];
    const float* bh1 = (const float*)d_in[8];
    const float* Wz1 = (const float*)d_in[9];
    const float* bz1 = (const float*)d_in[10];
    const float* Uh1 = (const float*)d_in[11];
    const float* Uz1 = (const float*)d_in[12];
    float* out = (float*)d_out;

    float *p_wh, *p_wz, *p_h1, *p_hbuf, *p_zhbuf;
    unsigned int* p_bar;
    cudaGetSymbolAddress((void**)&p_wh, g_wh);
    cudaGetSymbolAddress((void**)&p_wz, g_wz);
    cudaGetSymbolAddress((void**)&p_h1, g_h1);
    cudaGetSymbolAddress((void**)&p_hbuf, g_hbuf);
    cudaGetSymbolAddress((void**)&p_zhbuf, g_zhbuf);
    cudaGetSymbolAddress((void**)&p_bar, g_bar);

    cudaFuncSetAttribute(scan_kernel, cudaFuncAttributeMaxDynamicSharedMemorySize,
                         SCAN_SMEM_BYTES);

    dim3 pgrid(8, 2000);

    // ---- Layer 0 ----
    proj_kernel<<<pgrid, 256>>>(x, Wh0, Wz0, bh0, bz0, p_wh, p_wz);
    cudaMemsetAsync(p_hbuf, 0, B_*H_*sizeof(float));
    cudaMemsetAsync(p_bar, 0, 8*sizeof(unsigned int));
    scan_kernel<<<128, 256, SCAN_SMEM_BYTES>>>(p_wh, p_wz, Uh0, Uz0,
                                               p_h1, p_hbuf, p_zhbuf, p_bar);

    // ---- Layer 1 ----
    proj_kernel<<<pgrid, 256>>>(p_h1, Wh1, Wz1, bh1, bz1, p_wh, p_wz);
    cudaMemsetAsync(p_hbuf, 0, B_*H_*sizeof(float));
    cudaMemsetAsync(p_bar, 0, 8*sizeof(unsigned int));
    scan_kernel<<<128, 256, SCAN_SMEM_BYTES>>>(p_wh, p_wz, Uh1, Uz1,
                                               out, p_hbuf, p_zhbuf, p_bar);
}

// round 2
// speedup vs baseline: 1.2398x; 1.2398x over previous
#include <cuda_runtime.h>
#include <math.h>

#define T_ 2000
#define B_ 64
#define D_ 512
#define H_ 512
#define TB_ (T_*B_)

// ---- scratch (static device allocations; no cudaMalloc allowed) ----
__device__ float g_wh[TB_*H_];       // 262 MB
__device__ float g_wz[TB_*H_];       // 262 MB
__device__ float g_h1[TB_*H_];       // 262 MB (layer-1 input = layer-0 output)
__device__ float g_hT[H_*B_];        // hidden state, TRANSPOSED [j][64 b]
__device__ float g_zhT[H_*B_];       // z*h staging, TRANSPOSED [j][64 b]
__device__ unsigned int g_bar[8];    // one barrier counter per batch-group

// =====================================================================
// Stage A: fused dual projection  owh = X@Wh^T + bh, owz = X@Wz^T + bz
// (unchanged from round 1 — ~10ms for both layers; tensor-core later)
// =====================================================================
__global__ void __launch_bounds__(256) proj_kernel(
    const float* __restrict__ X,
    const float* __restrict__ Wh, const float* __restrict__ Wz,
    const float* __restrict__ bh, const float* __restrict__ bz,
    float* __restrict__ owh, float* __restrict__ owz)
{
    __shared__ float As[32*64];
    __shared__ float Bhs[32*64];
    __shared__ float Bzs[32*64];

    const int tid = threadIdx.x;
    const int n0 = blockIdx.x * 64;
    const long m0 = (long)blockIdx.y * 64;
    const int pm = tid & 15;
    const int pn = tid >> 4;

    float ah[4][4], az[4][4];
#pragma unroll
    for (int i = 0; i < 4; i++)
#pragma unroll
        for (int j = 0; j < 4; j++) { ah[i][j] = 0.f; az[i][j] = 0.f; }

    for (int k0 = 0; k0 < 512; k0 += 32) {
        __syncthreads();
#pragma unroll
        for (int q = 0; q < 2; q++) {
            int c = tid + 256*q;
            int row = c >> 3;
            int col4 = (c & 7) * 4;
            float4 xa = *(const float4*)&X[(m0 + row)*512 + k0 + col4];
            As[(col4+0)*64+row] = xa.x; As[(col4+1)*64+row] = xa.y;
            As[(col4+2)*64+row] = xa.z; As[(col4+3)*64+row] = xa.w;
            float4 wa = *(const float4*)&Wh[(long)(n0 + row)*512 + k0 + col4];
            Bhs[(col4+0)*64+row] = wa.x; Bhs[(col4+1)*64+row] = wa.y;
            Bhs[(col4+2)*64+row] = wa.z; Bhs[(col4+3)*64+row] = wa.w;
            float4 za = *(const float4*)&Wz[(long)(n0 + row)*512 + k0 + col4];
            Bzs[(col4+0)*64+row] = za.x; Bzs[(col4+1)*64+row] = za.y;
            Bzs[(col4+2)*64+row] = za.z; Bzs[(col4+3)*64+row] = za.w;
        }
        __syncthreads();
#pragma unroll
        for (int kk = 0; kk < 32; kk++) {
            float4 a  = *(float4*)&As [kk*64 + pm*4];
            float4 bh4 = *(float4*)&Bhs[kk*64 + pn*4];
            float4 bz4 = *(float4*)&Bzs[kk*64 + pn*4];
            float av[4] = {a.x, a.y, a.z, a.w};
            float hv[4] = {bh4.x, bh4.y, bh4.z, bh4.w};
            float zv[4] = {bz4.x, bz4.y, bz4.z, bz4.w};
#pragma unroll
            for (int i = 0; i < 4; i++)
#pragma unroll
                for (int j = 0; j < 4; j++) {
                    ah[i][j] += av[i]*hv[j];
                    az[i][j] += av[i]*zv[j];
                }
        }
    }

    float bb_h[4], bb_z[4];
#pragma unroll
    for (int j = 0; j < 4; j++) { bb_h[j] = bh[n0 + pn*4 + j]; bb_z[j] = bz[n0 + pn*4 + j]; }
#pragma unroll
    for (int i = 0; i < 4; i++) {
        long r = (m0 + pm*4 + i)*512 + n0 + pn*4;
        float4 oh, oz;
        oh.x = ah[i][0]+bb_h[0]; oh.y = ah[i][1]+bb_h[1];
        oh.z = ah[i][2]+bb_h[2]; oh.w = ah[i][3]+bb_h[3];
        oz.x = az[i][0]+bb_z[0]; oz.y = az[i][1]+bb_z[1];
        oz.z = az[i][2]+bb_z[2]; oz.w = az[i][3]+bb_z[3];
        *(float4*)&owh[r] = oh;
        *(float4*)&owz[r] = oz;
    }
}

// =====================================================================
// Stage B: persistent GRU scan, round-2 rework.
// Grid: 128 CTAs = 8 batch-groups (8 batches) x 16 H-slices (32 H).
// Exchange buffers are TRANSPOSED [j][64] so:
//   - producer store: 1 scalar STG per thread (sector-packed per group)
//   - consumer load : warp-local, float4, fully sector-efficient (__ldcg)
//   - SMEM staging  : conflict-free STS.128 / broadcast LDS.128
// h_prev for z*h lives in a register (same thread produced it last step).
// =====================================================================
#define SCAN_SMEM_BYTES ((64+64+16+16)*1024)

__global__ void __launch_bounds__(256) scan_kernel(
    const float* __restrict__ wh, const float* __restrict__ wz,
    const float* __restrict__ Uh, const float* __restrict__ Uz,
    float* __restrict__ out,
    float* __restrict__ hT, float* __restrict__ zhT,
    unsigned int* __restrict__ bar)
{
    extern __shared__ float sm[];
    float* Uzs = sm;                  // 512*32
    float* Uhs = sm + 16384;          // 512*32
    float* hx  = sm + 32768;          // 512*8  : [j][8 b]
    float* red = sm + 32768 + 4096;   // 16*256 partials

    const int tid  = threadIdx.x;
    const int gb   = blockIdx.x >> 4;   // batch group 0..7
    const int gh   = blockIdx.x & 15;   // H slice 0..15
    const int b0   = gb * 8;
    const int i0   = gh * 32;
    const int warp = tid >> 5;
    const int lane = tid & 31;

    // one-time U slice load (j-major)
    for (int idx = tid; idx < 32*512; idx += 256) {
        int i = idx >> 9;
        int j = idx & 511;
        Uzs[j*32 + i] = Uz[(i0 + i)*512 + j];
        Uhs[j*32 + i] = Uh[(i0 + i)*512 + j];
    }
    __syncthreads();

    // GEMM layout: ks = K-split (32 j each); warp covers j in [warp*64, warp*64+64)
    const int ks = tid >> 4;
    const int pos = tid & 15;
    const int pb = pos >> 3;          // batch quad 0..1
    const int pi = pos & 7;           // i quad 0..7
    const int jbase = ks * 32;

    // output ownership: 1 result per thread
    const int bl = tid >> 5;          // local batch 0..7
    const int il = tid & 31;          // local i 0..31
    const int jg = i0 + il;
    const int xpos = jg*64 + b0 + bl; // index into transposed exchange bufs

    unsigned int* barp = bar + gb;
    float h_own = 0.f;                // h(t-1) at (b0+bl, jg)

    for (int t = 0; t < T_; t++) {
        long base = ((long)(t*B_) + b0 + bl)*(long)H_ + jg;
        float wzv = __ldcg(wz + base);   // in flight during spin
        float whv = __ldcg(wh + base);

        // ================= phase Z =================
        if (tid == 0) {
            unsigned tgt = (unsigned)(2*t) * 16u;
            while (*(volatile unsigned*)barp < tgt) {}
            __threadfence();
        }
        __syncthreads();

        // stage h(t-1): warp-local slice of hT
#pragma unroll
        for (int it = 0; it < 4; it++) {
            int fq = it*32 + lane;           // 0..127
            int j  = (warp << 6) + (fq >> 1);
            int hf = fq & 1;
            float4 v = __ldcg((const float4*)(hT + j*64 + b0 + hf*4));
            *(float4*)(hx + j*8 + hf*4) = v;
        }
        __syncwarp();

        // GEMM z partials
        float a00,a01,a02,a03,a10,a11,a12,a13,a20,a21,a22,a23,a30,a31,a32,a33;
        a00=a01=a02=a03=a10=a11=a12=a13=a20=a21=a22=a23=a30=a31=a32=a33=0.f;
        {
            const float* hp = hx + jbase*8 + pb*4;
            const float* up = Uzs + jbase*32 + pi*4;
#pragma unroll
            for (int kk = 0; kk < 32; kk++) {
                float4 hv = *(const float4*)hp; hp += 8;
                float4 uv = *(const float4*)up; up += 32;
                a00 += hv.x*uv.x; a01 += hv.x*uv.y; a02 += hv.x*uv.z; a03 += hv.x*uv.w;
                a10 += hv.y*uv.x; a11 += hv.y*uv.y; a12 += hv.y*uv.z; a13 += hv.y*uv.w;
                a20 += hv.z*uv.x; a21 += hv.z*uv.y; a22 += hv.z*uv.z; a23 += hv.z*uv.w;
                a30 += hv.w*uv.x; a31 += hv.w*uv.y; a32 += hv.w*uv.z; a33 += hv.w*uv.w;
            }
        }
        {
            float* rp = red + ks*256 + pb*128 + pi*4;
            *(float4*)(rp      ) = make_float4(a00,a01,a02,a03);
            *(float4*)(rp + 32 ) = make_float4(a10,a11,a12,a13);
            *(float4*)(rp + 64 ) = make_float4(a20,a21,a22,a23);
            *(float4*)(rp + 96 ) = make_float4(a30,a31,a32,a33);
        }
        __syncthreads();

        float s = 0.f;
#pragma unroll
        for (int k2 = 0; k2 < 16; k2++) s += red[k2*256 + tid];

        float z  = __fdividef(1.f, 1.f + __expf(-(s + wzv)));
        float zh = z * h_own;
        zhT[xpos] = zh;
        __syncthreads();
        if (tid == 0) { __threadfence(); atomicAdd(barp, 1u); }

        // ================= phase H =================
        if (tid == 0) {
            unsigned tgt = (unsigned)(2*t + 1) * 16u;
            while (*(volatile unsigned*)barp < tgt) {}
            __threadfence();
        }
        __syncthreads();

#pragma unroll
        for (int it = 0; it < 4; it++) {
            int fq = it*32 + lane;
            int j  = (warp << 6) + (fq >> 1);
            int hf = fq & 1;
            float4 v = __ldcg((const float4*)(zhT + j*64 + b0 + hf*4));
            *(float4*)(hx + j*8 + hf*4) = v;
        }
        __syncwarp();

        a00=a01=a02=a03=a10=a11=a12=a13=a20=a21=a22=a23=a30=a31=a32=a33=0.f;
        {
            const float* hp = hx + jbase*8 + pb*4;
            const float* up = Uhs + jbase*32 + pi*4;
#pragma unroll
            for (int kk = 0; kk < 32; kk++) {
                float4 hv = *(const float4*)hp; hp += 8;
                float4 uv = *(const float4*)up; up += 32;
                a00 += hv.x*uv.x; a01 += hv.x*uv.y; a02 += hv.x*uv.z; a03 += hv.x*uv.w;
                a10 += hv.y*uv.x; a11 += hv.y*uv.y; a12 += hv.y*uv.z; a13 += hv.y*uv.w;
                a20 += hv.z*uv.x; a21 += hv.z*uv.y; a22 += hv.z*uv.z; a23 += hv.z*uv.w;
                a30 += hv.w*uv.x; a31 += hv.w*uv.y; a32 += hv.w*uv.z; a33 += hv.w*uv.w;
            }
        }
        {
            float* rp = red + ks*256 + pb*128 + pi*4;
            *(float4*)(rp      ) = make_float4(a00,a01,a02,a03);
            *(float4*)(rp + 32 ) = make_float4(a10,a11,a12,a13);
            *(float4*)(rp + 64 ) = make_float4(a20,a21,a22,a23);
            *(float4*)(rp + 96 ) = make_float4(a30,a31,a32,a33);
        }
        __syncthreads();

        float s2 = 0.f;
#pragma unroll
        for (int k2 = 0; k2 < 16; k2++) s2 += red[k2*256 + tid];

        float ahv = s2 + whv;
        // tanh(a) = 2/(1+exp(-2a)) - 1
        float hc = __fdividef(2.f, 1.f + __expf(-2.f*ahv)) - 1.f;
        float hn = zh + (1.f - z)*hc;
        h_own = hn;
        hT[xpos] = hn;
        out[base] = hn;
        __syncthreads();
        if (tid == 0) { __threadfence(); atomicAdd(barp, 1u); }
    }
}

// =====================================================================
extern "C" void kernel_launch(void* const* d_in, const int* in_sizes, int n_in,
                              void* d_out, int out_size)
{
    const float* x   = (const float*)d_in[0];
    const float* Wh0 = (const float*)d_in[1];
    const float* bh0 = (const float*)d_in[2];
    const float* Wz0 = (const float*)d_in[3];
    const float* bz0 = (const float*)d_in[4];
    const float* Uh0 = (const float*)d_in[5];
    const float* Uz0 = (const float*)d_in[6];
    const float* Wh1 = (const float*)d_in[7];
    const float* bh1 = (const float*)d_in[8];
    const float* Wz1 = (const float*)d_in[9];
    const float* bz1 = (const float*)d_in[10];
    const float* Uh1 = (const float*)d_in[11];
    const float* Uz1 = (const float*)d_in[12];
    float* out = (float*)d_out;

    float *p_wh, *p_wz, *p_h1, *p_hT, *p_zhT;
    unsigned int* p_bar;
    cudaGetSymbolAddress((void**)&p_wh, g_wh);
    cudaGetSymbolAddress((void**)&p_wz, g_wz);
    cudaGetSymbolAddress((void**)&p_h1, g_h1);
    cudaGetSymbolAddress((void**)&p_hT, g_hT);
    cudaGetSymbolAddress((void**)&p_zhT, g_zhT);
    cudaGetSymbolAddress((void**)&p_bar, g_bar);

    cudaFuncSetAttribute(scan_kernel, cudaFuncAttributeMaxDynamicSharedMemorySize,
                         SCAN_SMEM_BYTES);

    dim3 pgrid(8, 2000);

    // ---- Layer 0 ----
    proj_kernel<<<pgrid, 256>>>(x, Wh0, Wz0, bh0, bz0, p_wh, p_wz);
    cudaMemsetAsync(p_hT, 0, H_*B_*sizeof(float));
    cudaMemsetAsync(p_bar, 0, 8*sizeof(unsigned int));
    scan_kernel<<<128, 256, SCAN_SMEM_BYTES>>>(p_wh, p_wz, Uh0, Uz0,
                                               p_h1, p_hT, p_zhT, p_bar);

    // ---- Layer 1 ----
    proj_kernel<<<pgrid, 256>>>(p_h1, Wh1, Wz1, bh1, bz1, p_wh, p_wz);
    cudaMemsetAsync(p_hT, 0, H_*B_*sizeof(float));
    cudaMemsetAsync(p_bar, 0, 8*sizeof(unsigned int));
    scan_kernel<<<128, 256, SCAN_SMEM_BYTES>>>(p_wh, p_wz, Uh1, Uz1,
                                               out, p_hT, p_zhT, p_bar);
}